// round 7
// baseline (speedup 1.0000x reference)
#include <cuda_runtime.h>

// Problem constants (fixed by the reference):
//   B=32768, LMAX=24, M=10, D=300, V=36
#define BB    32768
#define LMAXC 24
#define MC    10
#define D4C   75          // D / 4 float4s per (b,m) row

// One warp per PAIR of rows (b, 2j) and (b, 2j+1). 8 warps / 256-thread block.
// Total warps = B * 5 = 163840 -> 20480 blocks (exact).
__global__ __launch_bounds__(256)
void word_emb_kernel(const float4* __restrict__ emb,     // [36, 75] float4
                     const float4* __restrict__ pad,     // [75] float4
                     const int*    __restrict__ tokens,  // [B, 24]
                     const int*    __restrict__ lengths, // [B]
                     float4*       __restrict__ out)     // [B*10, 75] float4
{
    const int gw   = (blockIdx.x * 256 + threadIdx.x) >> 5;  // 0 .. B*5-1
    const int lane = threadIdx.x & 31;
    const int b    = gw / 5;
    const int j    = gw - b * 5;
    const int m0   = j * 2;                                  // rows m0, m0+1

    const int L = __ldg(lengths + b);                        // warp-uniform
    const int* tok_row = tokens + b * LMAXC;
    float4* o0 = out + ((long long)b * MC + m0) * D4C;       // row m0; row m1 at +75

    if (L < MC) {
        // ---- padding branch: row m is token-m embedding if m < L, else pad vec
        const float4* s0 = (m0     < L) ? (emb + __ldg(tok_row + m0)     * D4C) : pad;
        const float4* s1 = (m0 + 1 < L) ? (emb + __ldg(tok_row + m0 + 1) * D4C) : pad;

        const float4 v00 = s0[lane];
        const float4 v01 = s0[lane + 32];
        const float4 v10 = s1[lane];
        const float4 v11 = s1[lane + 32];
        __stcs(o0 + lane,           v00);
        __stcs(o0 + lane + 32,      v01);
        __stcs(o0 + D4C + lane,      v10);
        __stcs(o0 + D4C + lane + 32, v11);
        if (lane < D4C - 64) {
            const float4 v02 = s0[lane + 64];
            const float4 v12 = s1[lane + 64];
            __stcs(o0 + lane + 64,       v02);
            __stcs(o0 + D4C + lane + 64, v12);
        }
    } else {
        // ---- interpolate branch: src = m*(L-1)/9, align_corners (fp32 as in ref)
        const float pos0 = (float)(m0 * (L - 1)) / 9.0f;
        const int   lo0  = (int)pos0;
        const int   hi0  = min(lo0 + 1, L - 1);
        const float w0   = pos0 - (float)lo0;
        const float n0   = 1.0f - w0;

        const float pos1 = (float)((m0 + 1) * (L - 1)) / 9.0f;
        const int   lo1  = (int)pos1;
        const int   hi1  = min(lo1 + 1, L - 1);
        const float w1   = pos1 - (float)lo1;
        const float n1   = 1.0f - w1;

        const int tlo0 = __ldg(tok_row + lo0);
        const int thi0 = __ldg(tok_row + hi0);
        const int tlo1 = __ldg(tok_row + lo1);
        const int thi1 = __ldg(tok_row + hi1);
        const float4* ea0 = emb + tlo0 * D4C;
        const float4* eb0 = emb + thi0 * D4C;
        const float4* ea1 = emb + tlo1 * D4C;
        const float4* eb1 = emb + thi1 * D4C;

        // batch all main-body loads up front (8 independent LDG.128)
        const float4 A00 = ea0[lane];
        const float4 B00 = eb0[lane];
        const float4 A01 = ea0[lane + 32];
        const float4 B01 = eb0[lane + 32];
        const float4 A10 = ea1[lane];
        const float4 B10 = eb1[lane];
        const float4 A11 = ea1[lane + 32];
        const float4 B11 = eb1[lane + 32];

        float4 r;
        r.x = A00.x * n0 + B00.x * w0;  r.y = A00.y * n0 + B00.y * w0;
        r.z = A00.z * n0 + B00.z * w0;  r.w = A00.w * n0 + B00.w * w0;
        __stcs(o0 + lane, r);
        r.x = A01.x * n0 + B01.x * w0;  r.y = A01.y * n0 + B01.y * w0;
        r.z = A01.z * n0 + B01.z * w0;  r.w = A01.w * n0 + B01.w * w0;
        __stcs(o0 + lane + 32, r);
        r.x = A10.x * n1 + B10.x * w1;  r.y = A10.y * n1 + B10.y * w1;
        r.z = A10.z * n1 + B10.z * w1;  r.w = A10.w * n1 + B10.w * w1;
        __stcs(o0 + D4C + lane, r);
        r.x = A11.x * n1 + B11.x * w1;  r.y = A11.y * n1 + B11.y * w1;
        r.z = A11.z * n1 + B11.z * w1;  r.w = A11.w * n1 + B11.w * w1;
        __stcs(o0 + D4C + lane + 32, r);

        if (lane < D4C - 64) {
            const float4 A02 = ea0[lane + 64];
            const float4 B02 = eb0[lane + 64];
            const float4 A12 = ea1[lane + 64];
            const float4 B12 = eb1[lane + 64];
            float4 t;
            t.x = A02.x * n0 + B02.x * w0;  t.y = A02.y * n0 + B02.y * w0;
            t.z = A02.z * n0 + B02.z * w0;  t.w = A02.w * n0 + B02.w * w0;
            __stcs(o0 + lane + 64, t);
            t.x = A12.x * n1 + B12.x * w1;  t.y = A12.y * n1 + B12.y * w1;
            t.z = A12.z * n1 + B12.z * w1;  t.w = A12.w * n1 + B12.w * w1;
            __stcs(o0 + D4C + lane + 64, t);
        }
    }
}

extern "C" void kernel_launch(void* const* d_in, const int* in_sizes, int n_in,
                              void* d_out, int out_size)
{
    const float4* emb     = (const float4*)d_in[0];  // emb_table [36, 300] f32
    const float4* pad     = (const float4*)d_in[1];  // pad_table [1, 300] f32
    const int*    tokens  = (const int*)d_in[2];     // tokens [32768, 24] i32
    const int*    lengths = (const int*)d_in[3];     // lengths [32768] i32
    float4*       out     = (float4*)d_out;          // [32768, 10, 300] f32

    const int nwarps = BB * 5;                       // 163,840 warps (2 rows each)
    const int blocks = nwarps / 8;                   // 20,480 blocks of 256 (exact)
    word_emb_kernel<<<blocks, 256>>>(emb, pad, tokens, lengths, out);
}